// round 13
// baseline (speedup 1.0000x reference)
#include <cuda_runtime.h>
#include <cuda_fp16.h>
#include <cstdint>

#define DD 64
#define LL 128
#define KROWS 8192
#define MROWS 64
#define NBLK (KROWS/MROWS)   // 128 CTAs
#define NTHR 512

typedef unsigned int u32;

// smem byte offsets
#define SM_A0  0          // h buf0: 64 rows x 128B (fp16)
#define SM_A1  8192
#define SM_BH  16384      // W fp16: 256 n-rows x 128B (32KB); later sWa/sWf
#define SM_X   49152      // x: 64 x 129 floats = 33024B; later sHfin/sCst
#define SM_CA  82176      // 256 floats
#define SM_CB  83200      // 256 floats
#define SM_RED 84224      // 128 floats
#define SM_FIN 84736      // 3*64 floats
#define SM_FLG 85504      // 4B
#define SM_TOT 85568

__device__ float g_acc[128];
__device__ unsigned int g_ctr = 0;

__device__ __forceinline__ float fexp(float x){
    x = fmaxf(fminf(x, 30.f), -30.f);
    return __expf(x);
}
__device__ __forceinline__ float sigf(float x){
    return __fdividef(1.0f, 1.0f + fexp(-x));
}
__device__ __forceinline__ float tanhp(float x){
    return 2.0f * __fdividef(1.0f, 1.0f + fexp(-2.0f*x)) - 1.0f;
}
__device__ __forceinline__ float tanha(float x){
    float r; asm("tanh.approx.f32 %0, %1;" : "=f"(r) : "f"(x)); return r;
}
__device__ __forceinline__ float siga(float x){
    return fmaf(0.5f, tanha(0.5f*x), 0.5f);
}

__device__ __forceinline__ void mma_fp16(float* c, const u32* a, const u32* b){
    asm volatile("mma.sync.aligned.m16n8k16.row.col.f32.f16.f16.f32 "
        "{%0,%1,%2,%3}, {%4,%5,%6,%7}, {%8,%9}, {%0,%1,%2,%3};\n"
        : "+f"(c[0]),"+f"(c[1]),"+f"(c[2]),"+f"(c[3])
        : "r"(a[0]),"r"(a[1]),"r"(a[2]),"r"(a[3]), "r"(b[0]),"r"(b[1]));
}

// ---------- fused kernel: pair-split epilogue + warp-parity stagger ----------
// Column order: n = wn*32 + p*16 + q*8 + c ; gate G = 2q + (c&1); d = wn*8 + p*4 + (c>>1)
__global__ void __launch_bounds__(NTHR,1)
lstm_kernel(const float* __restrict__ x,
            const float* __restrict__ W_num,  const float* __restrict__ b_num,
            const float* __restrict__ W_ih,   const float* __restrict__ W_hh,
            const float* __restrict__ b_ih,   const float* __restrict__ b_hh,
            const float* __restrict__ W_aout, const float* __restrict__ b_aout,
            const float* __restrict__ W_fh,   const float* __restrict__ b_fh,
            const float* __restrict__ W_iouh, const float* __restrict__ b_iouh,
            const float* __restrict__ W_oout, const float* __restrict__ b_oout,
            float* __restrict__ out){
    extern __shared__ char sm[];
    const int tid  = threadIdx.x;
    const int wid  = tid >> 5;
    const int lane = tid & 31;
    const int g    = lane >> 2;      // 0..7
    const int tq   = lane & 3;       // 0..3
    const int mh   = wid & 1;        // rows mh*32 + {0..31} (two m16 subs)
    const int wn   = wid >> 1;       // 0..7: 8 d's (d = wn*8 + p*4 + tq)
    const int par  = wid & 1;        // stagger parity
    const u32 xorv = (u32)g << 4;
    const int r0   = blockIdx.x * MROWS;

    float* sXf = (float*)(sm + SM_X);
    float* sCa = (float*)(sm + SM_CA);
    float* sCb = (float*)(sm + SM_CB);
    float* sRd = (float*)(sm + SM_RED);

    // ---- prep: consts + fp16 W (reordered + swizzled) ----
    if (tid < 256){
        int n = tid;
        int wn2 = n >> 5;
        int r5  = n & 31;
        int p   = (r5 >> 4) & 1;
        int q   = (r5 >> 3) & 1;
        int c   = r5 & 7;
        int G   = 2*q + (c & 1);
        int d   = wn2*8 + p*4 + (c >> 1);
        int wr  = G*64 + d;
        float sa = 0.f, sc = 0.f;
        #pragma unroll 8
        for (int k = 0; k < DD; k++){
            float w = __ldg(W_ih + wr*(2*DD) + k);
            sa += w * __ldg(W_num + k);
            sc += w * __ldg(b_num + k);
        }
        sCa[n] = sa;
        sCb[n] = sc + __ldg(b_ih + wr) + __ldg(b_hh + wr);
        #pragma unroll 8
        for (int k = 0; k < DD; k++){
            float w = __ldg(W_hh + wr*DD + k);
            u32 off = (u32)n*128 + (u32)k*2;
            u32 sw  = off ^ (((u32)n & 7u) << 4);
            *(__half*)(sm + SM_BH + sw) = __float2half_rn(w);
        }
    }
    {
        uint4 z = make_uint4(0,0,0,0);
        uint4* da = (uint4*)(sm + SM_A0);
        for (int i = tid; i < 1024; i += NTHR) da[i] = z;   // A0+A1 (16KB)
        for (int idx = tid; idx < MROWS*LL; idx += NTHR){
            int rr = idx >> 7, tt = idx & 127;
            sXf[rr*129 + tt] = x[(size_t)(r0 + rr)*LL + tt];
        }
        if (tid < 128) sRd[tid] = 0.f;
    }
    __syncthreads();

    // ---- stationary B fragments ----
    u32 breg[2][2][4][2];    // [p][q][k4][2]
    {
        const char* Bs0 = sm + SM_BH + (size_t)((wn*32 + g) * 128);
        #pragma unroll
        for (int p = 0; p < 2; p++)
            #pragma unroll
            for (int q = 0; q < 2; q++)
                #pragma unroll
                for (int k4 = 0; k4 < 4; k4++){
                    u32 o0 = ((u32)(32*k4 + 4*tq)) ^ xorv;
                    breg[p][q][k4][0] = *(const u32*)(Bs0 + p*2048 + q*1024 + o0);
                    breg[p][q][k4][1] = *(const u32*)(Bs0 + p*2048 + q*1024 + (o0^16));
                }
    }

    float creg[8];
    #pragma unroll
    for (int i = 0; i < 8; i++) creg[i] = 0.f;

    const int dbase = wn*8 + tq;

    for (int t = 0; t < LL; t++){
        const char* Ah = sm + ((t & 1) ? SM_A1 : SM_A0);
        char* Aw = sm + ((t & 1) ? SM_A0 : SM_A1);

        float xv[2][2];
        #pragma unroll
        for (int sub = 0; sub < 2; sub++)
            #pragma unroll
            for (int s = 0; s < 2; s++)
                xv[sub][s] = sXf[(mh*32 + sub*16 + g + s*8)*129 + t];

        #pragma unroll
        for (int pidx = 0; pidx < 2; pidx++){
            const int p = pidx ^ par;          // stagger: odd warps do pair1 first
            float acc[2][2][4];
            #pragma unroll
            for (int a1 = 0; a1 < 2; a1++)
                #pragma unroll
                for (int a2 = 0; a2 < 2; a2++)
                    #pragma unroll
                    for (int a3 = 0; a3 < 4; a3++) acc[a1][a2][a3] = 0.f;

            #pragma unroll
            for (int k4 = 0; k4 < 4; k4++){
                u32 o0 = ((u32)(32*k4 + 4*tq)) ^ xorv;
                u32 o8 = o0 ^ 16u;
                #pragma unroll
                for (int sub = 0; sub < 2; sub++){
                    const char* Ar = Ah + (mh*32 + sub*16 + g)*128;
                    u32 a[4];
                    a[0] = *(const u32*)(Ar +        o0);
                    a[1] = *(const u32*)(Ar + 1024 + o0);
                    a[2] = *(const u32*)(Ar +        o8);
                    a[3] = *(const u32*)(Ar + 1024 + o8);
                    mma_fp16(acc[sub][0], a, breg[p][0][k4]);
                    mma_fp16(acc[sub][1], a, breg[p][1][k4]);
                }
            }

            // epilogue for this pair: thread owns d = wn*8 + p*4 + tq, all 4 gates
            int n_if = wn*32 + p*16 + 2*tq;
            float2 aIF = *(const float2*)(sCa + n_if);
            float2 aGO = *(const float2*)(sCa + n_if + 8);
            float2 cIF = *(const float2*)(sCb + n_if);
            float2 cGO = *(const float2*)(sCb + n_if + 8);
            const int d = dbase + p*4;
            #pragma unroll
            for (int sub = 0; sub < 2; sub++){
                #pragma unroll
                for (int s = 0; s < 2; s++){
                    float xvv = xv[sub][s];
                    float gi = acc[sub][0][2*s    ] + fmaf(aIF.x, xvv, cIF.x);
                    float gf = acc[sub][0][2*s + 1] + fmaf(aIF.y, xvv, cIF.y);
                    float gg = acc[sub][1][2*s    ] + fmaf(aGO.x, xvv, cGO.x);
                    float go = acc[sub][1][2*s + 1] + fmaf(aGO.y, xvv, cGO.y);
                    int ci = p*4 + sub*2 + s;
                    float c2 = siga(gf)*creg[ci] + siga(gi)*tanha(gg);
                    creg[ci] = c2;
                    float h = siga(go)*tanha(c2);
                    int r = mh*32 + sub*16 + g + s*8;
                    u32 off = ((u32)(r*128 + d*2)) ^ xorv;
                    *(__half*)(Aw + off) = __float2half_rn(h);
                }
            }
        }
        __syncthreads();
    }

    // ---- final per-CTA stage ----
    float* sHfin = (float*)(sm + SM_X);            // [row][d] stride 64 (16KB)
    float* sCst  = (float*)(sm + SM_X + 16384);    // (16KB)
    #pragma unroll
    for (int p = 0; p < 2; p++){
        const int d = dbase + p*4;
        #pragma unroll
        for (int sub = 0; sub < 2; sub++){
            #pragma unroll
            for (int s = 0; s < 2; s++){
                int r = mh*32 + sub*16 + g + s*8;
                u32 off = ((u32)(r*128 + d*2)) ^ xorv;
                float h = __half2float(*(const __half*)(sm + SM_A0 + off));
                sHfin[r*64 + d] = h;
                sCst [r*64 + d] = creg[p*4 + sub*2 + s];
            }
        }
    }
    __syncthreads();
    float* sWa = (float*)(sm + SM_BH);
    float* sWf = sWa + 4096;
    for (int i = tid; i < 4096; i += NTHR){ sWa[i] = W_aout[i]; sWf[i] = W_fh[i]; }
    __syncthreads();

    float* sHhat = (float*)(sm + SM_A0);           // [row][d] stride 64 (16KB = A0+A1)
    const int row = tid >> 3;
    const int d0  = (tid & 7) << 3;
    #pragma unroll 2
    for (int jj = 0; jj < 8; jj++){
        int d = d0 + jj;
        float acc2 = __ldg(b_aout + d);
        #pragma unroll 8
        for (int e = 0; e < DD; e++) acc2 += sHfin[row*64 + e] * sWa[d*64 + e];
        sHhat[row*64 + d] = acc2;
        atomicAdd(&sRd[64 + d], acc2);
    }
    __syncthreads();
    #pragma unroll 2
    for (int jj = 0; jj < 8; jj++){
        int d = d0 + jj;
        float f = __ldg(b_fh + d);
        #pragma unroll 8
        for (int e = 0; e < DD; e++) f += sHhat[row*64 + e] * sWf[d*64 + e];
        atomicAdd(&sRd[d], sigf(f) * sCst[row*64 + d]);
    }
    __syncthreads();

    // ---- global reduction + last-CTA finisher ----
    if (tid < 128) atomicAdd(&g_acc[tid], sRd[tid]);
    __threadfence();
    __syncthreads();
    if (tid == 0){
        unsigned int rnk = atomicAdd(&g_ctr, 1);
        *(u32*)(sm + SM_FLG) = (rnk == NBLK - 1) ? 1u : 0u;
    }
    __syncthreads();
    if (*(const u32*)(sm + SM_FLG)){
        float* sfc = (float*)(sm + SM_FIN);
        float* shs = sfc + 64;
        float* sho = sfc + 128;
        if (tid < 64){ sfc[tid] = g_acc[tid]; shs[tid] = g_acc[64 + tid]; }
        __syncthreads();
        if (tid < 64){
            int d = tid;
            float vi = __ldg(b_iouh + d), vo = __ldg(b_iouh + 64 + d), vu = __ldg(b_iouh + 128 + d);
            #pragma unroll 8
            for (int e = 0; e < DD; e++){
                float h = shs[e];
                vi += h * __ldg(W_iouh + (      d)*64 + e);
                vo += h * __ldg(W_iouh + ( 64 + d)*64 + e);
                vu += h * __ldg(W_iouh + (128 + d)*64 + e);
            }
            float cobj = sigf(vi)*tanhp(vu) + sfc[d];
            sho[d] = sigf(vo)*tanhp(cobj);
            out[64 + d] = cobj;
        }
        __syncthreads();
        if (tid < 64){
            int d = tid;
            float acc3 = __ldg(b_oout + d);
            #pragma unroll 8
            for (int e = 0; e < DD; e++) acc3 += sho[e] * __ldg(W_oout + d*64 + e);
            out[d] = acc3;
        }
        if (tid < 128) g_acc[tid] = 0.f;
        __threadfence();
        if (tid == 0) g_ctr = 0;
    }
}

extern "C" void kernel_launch(void* const* d_in, const int* in_sizes, int n_in,
                              void* d_out, int out_size){
    const float* x      = (const float*)d_in[0];
    const float* W_num  = (const float*)d_in[1];
    const float* b_num  = (const float*)d_in[2];
    const float* W_ih   = (const float*)d_in[3];
    const float* W_hh   = (const float*)d_in[4];
    const float* b_ih   = (const float*)d_in[5];
    const float* b_hh   = (const float*)d_in[6];
    const float* W_aout = (const float*)d_in[7];
    const float* b_aout = (const float*)d_in[8];
    const float* W_fh   = (const float*)d_in[9];
    const float* b_fh   = (const float*)d_in[10];
    const float* W_iouh = (const float*)d_in[11];
    const float* b_iouh = (const float*)d_in[12];
    const float* W_oout = (const float*)d_in[13];
    const float* b_oout = (const float*)d_in[14];
    float* out = (float*)d_out;

    cudaFuncSetAttribute(lstm_kernel, cudaFuncAttributeMaxDynamicSharedMemorySize, SM_TOT);

    lstm_kernel<<<NBLK, NTHR, SM_TOT>>>(x, W_num, b_num, W_ih, W_hh, b_ih, b_hh,
                                        W_aout, b_aout, W_fh, b_fh,
                                        W_iouh, b_iouh, W_oout, b_oout, out);
}

// round 14
// speedup vs baseline: 1.1733x; 1.1733x over previous
#include <cuda_runtime.h>
#include <cuda_fp16.h>
#include <cstdint>

#define DD 64
#define LL 128
#define KROWS 8192
#define MROWS 64
#define NBLK (KROWS/MROWS)   // 128 CTAs
#define NTHR 512

typedef unsigned int u32;

// smem byte offsets
#define SM_A0  0          // h buf0: 64 rows x 128B (fp16)
#define SM_A1  8192
#define SM_BH  16384      // W fp16 staging: 256 n-rows x 128B (32KB); reused for sWa/sWf
#define SM_X   49152      // x: 64 x 129 floats = 33024B
#define SM_CA  82176      // 256 floats
#define SM_CB  83200      // 256 floats
#define SM_RED 84224      // 128 floats
#define SM_FIN 84736      // 3*64 floats
#define SM_FLG 85504      // 4B
#define SM_TOT 85568

__device__ float g_acc[128];
__device__ unsigned int g_ctr = 0;

__device__ __forceinline__ float fexp(float x){
    x = fmaxf(fminf(x, 30.f), -30.f);
    return __expf(x);
}
__device__ __forceinline__ float sigf(float x){
    return __fdividef(1.0f, 1.0f + fexp(-x));
}
__device__ __forceinline__ float tanhp(float x){
    return 2.0f * __fdividef(1.0f, 1.0f + fexp(-2.0f*x)) - 1.0f;
}
__device__ __forceinline__ float tanha(float x){
    float r; asm("tanh.approx.f32 %0, %1;" : "=f"(r) : "f"(x)); return r;
}
__device__ __forceinline__ float siga(float x){
    return fmaf(0.5f, tanha(0.5f*x), 0.5f);
}

__device__ __forceinline__ void mma_fp16(float* c, const u32* a, const u32* b){
    asm volatile("mma.sync.aligned.m16n8k16.row.col.f32.f16.f16.f32 "
        "{%0,%1,%2,%3}, {%4,%5,%6,%7}, {%8,%9}, {%0,%1,%2,%3};\n"
        : "+f"(c[0]),"+f"(c[1]),"+f"(c[2]),"+f"(c[3])
        : "r"(a[0]),"r"(a[1]),"r"(a[2]),"r"(a[3]), "r"(b[0]),"r"(b[1]));
}

// ---------- fused kernel: weight-stationary + per-SMSP anti-phase groups ----------
__global__ void __launch_bounds__(NTHR,1)
lstm_kernel(const float* __restrict__ x,
            const float* __restrict__ W_num,  const float* __restrict__ b_num,
            const float* __restrict__ W_ih,   const float* __restrict__ W_hh,
            const float* __restrict__ b_ih,   const float* __restrict__ b_hh,
            const float* __restrict__ W_aout, const float* __restrict__ b_aout,
            const float* __restrict__ W_fh,   const float* __restrict__ b_fh,
            const float* __restrict__ W_iouh, const float* __restrict__ b_iouh,
            const float* __restrict__ W_oout, const float* __restrict__ b_oout,
            float* __restrict__ out){
    extern __shared__ char sm[];
    const int tid  = threadIdx.x;
    const int wid  = tid >> 5;
    const int lane = tid & 31;
    const int g    = lane >> 2;      // group 0..7
    const int tq   = lane & 3;       // quad  0..3
    // KEY REMAP: dependency group alternates across warps of the SAME SMSP
    const int mtp  = (wid >> 2) & 1;                 // m-pair: rows mtp*32..
    const int wn   = (wid & 3) | ((wid >> 3) << 2);  // n 32-col chunk 0..7
    const u32 xorv = (u32)g << 4;
    const int r0   = blockIdx.x * MROWS;
    const int barid = mtp + 1;

    float* sXf = (float*)(sm + SM_X);
    float* sCa = (float*)(sm + SM_CA);
    float* sCb = (float*)(sm + SM_CB);
    float* sRd = (float*)(sm + SM_RED);

    // ---- per-CTA prep ----
    // Column order: n = wn2*32 + j*8 + c; gate = j; d = wn2*8 + c; W row = j*64 + d.
    if (tid < 256){
        int n = tid;
        int wn2 = n >> 5;
        int j = (n >> 3) & 3;
        int c = n & 7;
        int d  = wn2*8 + c;
        int wr = j*64 + d;
        float sa = 0.f, sc = 0.f;
        #pragma unroll 8
        for (int k = 0; k < DD; k++){
            float w = __ldg(W_ih + wr*(2*DD) + k);
            sa += w * __ldg(W_num + k);
            sc += w * __ldg(b_num + k);
        }
        sCa[n] = sa;
        sCb[n] = sc + __ldg(b_ih + wr) + __ldg(b_hh + wr);
        #pragma unroll 8
        for (int k = 0; k < DD; k++){
            float w = __ldg(W_hh + wr*DD + k);
            u32 off = (u32)n*128 + (u32)k*2;
            u32 sw  = off ^ (((u32)n & 7u) << 4);
            *(__half*)(sm + SM_BH + sw) = __float2half_rn(w);
        }
    }
    {
        uint4 z = make_uint4(0,0,0,0);
        uint4* da = (uint4*)(sm + SM_A0);
        for (int i = tid; i < 1024; i += NTHR) da[i] = z;   // A0+A1 (16KB)
        for (int idx = tid; idx < MROWS*LL; idx += NTHR){
            int rr = idx >> 7, tt = idx & 127;
            sXf[rr*129 + tt] = x[(size_t)(r0 + rr)*LL + tt];
        }
        if (tid < 128) sRd[tid] = 0.f;
    }
    __syncthreads();

    // ---- stationary B fragments in registers ----
    u32 breg[4][4][2];
    {
        const char* Bh0 = sm + SM_BH + (size_t)((wn*32 + g) * 128);
        #pragma unroll
        for (int k4 = 0; k4 < 4; k4++){
            u32 o0 = ((u32)(32*k4 + 4*tq)) ^ xorv;
            u32 o8 = o0 ^ 16u;
            #pragma unroll
            for (int j = 0; j < 4; j++){
                breg[j][k4][0] = *(const u32*)(Bh0 + j*1024 + o0);
                breg[j][k4][1] = *(const u32*)(Bh0 + j*1024 + o8);
            }
        }
    }
    // ---- hoisted loop-invariant gate constants ----
    float2 aJ[4], cJ[4];
    #pragma unroll
    for (int j = 0; j < 4; j++){
        int nI = wn*32 + j*8 + 2*tq;
        aJ[j] = *(const float2*)(sCa + nI);
        cJ[j] = *(const float2*)(sCb + nI);
    }

    float creg[8];
    #pragma unroll
    for (int i = 0; i < 8; i++) creg[i] = 0.f;

    const u32 cbS = ((u32)(wn*16 + 4*tq)) ^ xorv;

    for (int t = 0; t < LL; t++){
        const char* Ah = sm + ((t & 1) ? SM_A1 : SM_A0);
        char* Aw = sm + ((t & 1) ? SM_A0 : SM_A1);
        const char* ArH = Ah + mtp*4096 + g*128;

        float acc[32];
        #pragma unroll
        for (int i = 0; i < 32; i++) acc[i] = 0.f;

        #pragma unroll
        for (int k4 = 0; k4 < 4; k4++){
            u32 o0 = ((u32)(32*k4 + 4*tq)) ^ xorv;
            u32 o8 = o0 ^ 16u;
            u32 a0[4], a1[4];
            a0[0] = *(const u32*)(ArH +        o0);
            a0[1] = *(const u32*)(ArH + 1024 + o0);
            a0[2] = *(const u32*)(ArH +        o8);
            a0[3] = *(const u32*)(ArH + 1024 + o8);
            a1[0] = *(const u32*)(ArH + 2048 +        o0);
            a1[1] = *(const u32*)(ArH + 2048 + 1024 + o0);
            a1[2] = *(const u32*)(ArH + 2048 +        o8);
            a1[3] = *(const u32*)(ArH + 2048 + 1024 + o8);
            #pragma unroll
            for (int j = 0; j < 4; j++){
                mma_fp16(acc +      j*4, a0, breg[j][k4]);
                mma_fp16(acc + 16 + j*4, a1, breg[j][k4]);
            }
        }

        // ---- epilogue: gates -> (c,h), write h fp16 ----
        #pragma unroll
        for (int sub = 0; sub < 2; sub++){
            #pragma unroll
            for (int s = 0; s < 2; s++){
                int r = mtp*32 + sub*16 + g + s*8;
                float xv = sXf[r*129 + t];
                float h2[2];
                #pragma unroll
                for (int u = 0; u < 2; u++){
                    int fi = s*2 + u;
                    float gi = acc[sub*16 +  0 + fi] + fmaf(u?aJ[0].y:aJ[0].x, xv, u?cJ[0].y:cJ[0].x);
                    float gf = acc[sub*16 +  4 + fi] + fmaf(u?aJ[1].y:aJ[1].x, xv, u?cJ[1].y:cJ[1].x);
                    float gg = acc[sub*16 +  8 + fi] + fmaf(u?aJ[2].y:aJ[2].x, xv, u?cJ[2].y:cJ[2].x);
                    float go = acc[sub*16 + 12 + fi] + fmaf(u?aJ[3].y:aJ[3].x, xv, u?cJ[3].y:cJ[3].x);
                    int ci = sub*4 + s*2 + u;
                    float c2 = siga(gf)*creg[ci] + siga(gi)*tanha(gg);
                    creg[ci] = c2;
                    h2[u] = siga(go)*tanha(c2);
                }
                __half b0 = __float2half_rn(h2[0]);
                __half b1 = __float2half_rn(h2[1]);
                u32 hp = (u32)__half_as_ushort(b0) | ((u32)__half_as_ushort(b1) << 16);
                *(u32*)(Aw + r*128 + cbS) = hp;
            }
        }
        // per-group barrier: groups drift anti-phase on each SMSP
        asm volatile("bar.sync %0, %1;" :: "r"(barid), "r"(256) : "memory");
    }

    __syncthreads();   // rejoin both groups before buffer reuse

    // ---- final per-CTA stage ----
    float* sHfin = (float*)(sm + SM_X);            // [row][d] stride 64
    float* sCst  = (float*)(sm + SM_X + 16384);
    #pragma unroll
    for (int sub = 0; sub < 2; sub++){
        #pragma unroll
        for (int s = 0; s < 2; s++){
            #pragma unroll
            for (int u = 0; u < 2; u++){
                int r = mtp*32 + sub*16 + g + s*8;
                int d = wn*8 + 2*tq + u;
                u32 sw = ((u32)(2*d)) ^ xorv;
                float h = __half2float(*(const __half*)(sm + SM_A0 + r*128 + sw));
                sHfin[r*64 + d] = h;
                sCst [r*64 + d] = creg[sub*4 + s*2 + u];
            }
        }
    }
    __syncthreads();
    float* sWa = (float*)(sm + SM_BH);
    float* sWf = sWa + 4096;
    for (int i = tid; i < 4096; i += NTHR){ sWa[i] = W_aout[i]; sWf[i] = W_fh[i]; }
    __syncthreads();

    float* sHhat = (float*)(sm + SM_A0);           // [row][d] stride 64 (16KB = A0+A1)
    const int row = tid >> 3;
    const int d0  = (tid & 7) << 3;
    #pragma unroll 2
    for (int jj = 0; jj < 8; jj++){
        int d = d0 + jj;
        float acc2 = __ldg(b_aout + d);
        #pragma unroll 8
        for (int e = 0; e < DD; e++) acc2 += sHfin[row*64 + e] * sWa[d*64 + e];
        sHhat[row*64 + d] = acc2;
        atomicAdd(&sRd[64 + d], acc2);
    }
    __syncthreads();
    #pragma unroll 2
    for (int jj = 0; jj < 8; jj++){
        int d = d0 + jj;
        float f = __ldg(b_fh + d);
        #pragma unroll 8
        for (int e = 0; e < DD; e++) f += sHhat[row*64 + e] * sWf[d*64 + e];
        atomicAdd(&sRd[d], sigf(f) * sCst[row*64 + d]);
    }
    __syncthreads();

    // ---- global reduction + last-CTA finisher ----
    if (tid < 128) atomicAdd(&g_acc[tid], sRd[tid]);
    __threadfence();
    __syncthreads();
    if (tid == 0){
        unsigned int rnk = atomicAdd(&g_ctr, 1);
        *(u32*)(sm + SM_FLG) = (rnk == NBLK - 1) ? 1u : 0u;
    }
    __syncthreads();
    if (*(const u32*)(sm + SM_FLG)){
        float* sfc = (float*)(sm + SM_FIN);
        float* shs = sfc + 64;
        float* sho = sfc + 128;
        if (tid < 64){ sfc[tid] = g_acc[tid]; shs[tid] = g_acc[64 + tid]; }
        __syncthreads();
        if (tid < 64){
            int d = tid;
            float vi = __ldg(b_iouh + d), vo = __ldg(b_iouh + 64 + d), vu = __ldg(b_iouh + 128 + d);
            #pragma unroll 8
            for (int e = 0; e < DD; e++){
                float h = shs[e];
                vi += h * __ldg(W_iouh + (      d)*64 + e);
                vo += h * __ldg(W_iouh + ( 64 + d)*64 + e);
                vu += h * __ldg(W_iouh + (128 + d)*64 + e);
            }
            float cobj = sigf(vi)*tanhp(vu) + sfc[d];
            sho[d] = sigf(vo)*tanhp(cobj);
            out[64 + d] = cobj;
        }
        __syncthreads();
        if (tid < 64){
            int d = tid;
            float acc3 = __ldg(b_oout + d);
            #pragma unroll 8
            for (int e = 0; e < DD; e++) acc3 += sho[e] * __ldg(W_oout + d*64 + e);
            out[d] = acc3;
        }
        if (tid < 128) g_acc[tid] = 0.f;
        __threadfence();
        if (tid == 0) g_ctr = 0;
    }
}

extern "C" void kernel_launch(void* const* d_in, const int* in_sizes, int n_in,
                              void* d_out, int out_size){
    const float* x      = (const float*)d_in[0];
    const float* W_num  = (const float*)d_in[1];
    const float* b_num  = (const float*)d_in[2];
    const float* W_ih   = (const float*)d_in[3];
    const float* W_hh   = (const float*)d_in[4];
    const float* b_ih   = (const float*)d_in[5];
    const float* b_hh   = (const float*)d_in[6];
    const float* W_aout = (const float*)d_in[7];
    const float* b_aout = (const float*)d_in[8];
    const float* W_fh   = (const float*)d_in[9];
    const float* b_fh   = (const float*)d_in[10];
    const float* W_iouh = (const float*)d_in[11];
    const float* b_iouh = (const float*)d_in[12];
    const float* W_oout = (const float*)d_in[13];
    const float* b_oout = (const float*)d_in[14];
    float* out = (float*)d_out;

    cudaFuncSetAttribute(lstm_kernel, cudaFuncAttributeMaxDynamicSharedMemorySize, SM_TOT);

    lstm_kernel<<<NBLK, NTHR, SM_TOT>>>(x, W_num, b_num, W_ih, W_hh, b_ih, b_hh,
                                        W_aout, b_aout, W_fh, b_fh,
                                        W_iouh, b_iouh, W_oout, b_oout, out);
}

// round 15
// speedup vs baseline: 1.2351x; 1.0527x over previous
#include <cuda_runtime.h>
#include <cuda_fp16.h>
#include <cstdint>

#define DD 64
#define LL 128
#define KROWS 8192
#define MROWS 64
#define NBLK (KROWS/MROWS)   // 128 CTAs
#define NTHR 256

typedef unsigned int u32;

// smem byte offsets
#define SM_A0  0          // h buf0: 64 rows x 128B (fp16)
#define SM_A1  8192
#define SM_BH  16384      // W fp16 staging: 256 n-rows x 128B (32KB); reused for sWa/sWf
#define SM_X   49152      // x: 64 x 129 floats = 33024B
#define SM_CA  82176      // 256 floats
#define SM_CB  83200      // 256 floats
#define SM_RED 84224      // 128 floats
#define SM_FIN 84736      // 3*64 floats
#define SM_FLG 85504      // 4B
#define SM_TOT 85568

__device__ float g_acc[128];
__device__ unsigned int g_ctr = 0;

__device__ __forceinline__ float fexp(float x){
    x = fmaxf(fminf(x, 30.f), -30.f);
    return __expf(x);
}
__device__ __forceinline__ float sigf(float x){
    return __fdividef(1.0f, 1.0f + fexp(-x));
}
__device__ __forceinline__ float tanhp(float x){
    return 2.0f * __fdividef(1.0f, 1.0f + fexp(-2.0f*x)) - 1.0f;
}
__device__ __forceinline__ float tanha(float x){
    float r; asm("tanh.approx.f32 %0, %1;" : "=f"(r) : "f"(x)); return r;
}
__device__ __forceinline__ float siga(float x){
    return fmaf(0.5f, tanha(0.5f*x), 0.5f);
}

// D = A*B + C with D possibly != C  (chain-splitting form)
__device__ __forceinline__ void mma_dc(float* d, const float* c, const u32* a, const u32* b){
    asm volatile("mma.sync.aligned.m16n8k16.row.col.f32.f16.f16.f32 "
        "{%0,%1,%2,%3}, {%4,%5,%6,%7}, {%8,%9}, {%10,%11,%12,%13};\n"
        : "=f"(d[0]),"=f"(d[1]),"=f"(d[2]),"=f"(d[3])
        : "r"(a[0]),"r"(a[1]),"r"(a[2]),"r"(a[3]), "r"(b[0]),"r"(b[1]),
          "f"(c[0]),"f"(c[1]),"f"(c[2]),"f"(c[3]));
}

// ---------- fused kernel: weight-stationary, chain-split MMA, 2-stage pipeline ----------
__global__ void __launch_bounds__(NTHR,1)
lstm_kernel(const float* __restrict__ x,
            const float* __restrict__ W_num,  const float* __restrict__ b_num,
            const float* __restrict__ W_ih,   const float* __restrict__ W_hh,
            const float* __restrict__ b_ih,   const float* __restrict__ b_hh,
            const float* __restrict__ W_aout, const float* __restrict__ b_aout,
            const float* __restrict__ W_fh,   const float* __restrict__ b_fh,
            const float* __restrict__ W_iouh, const float* __restrict__ b_iouh,
            const float* __restrict__ W_oout, const float* __restrict__ b_oout,
            float* __restrict__ out){
    extern __shared__ char sm[];
    const int tid  = threadIdx.x;
    const int wid  = tid >> 5;
    const int lane = tid & 31;
    const int g    = lane >> 2;      // 0..7
    const int tq   = lane & 3;       // 0..3
    const int wn   = wid;            // n 32-col chunk 0..7 ; warp covers all 64 rows
    const u32 xorv = (u32)g << 4;
    const int r0   = blockIdx.x * MROWS;

    float* sXf = (float*)(sm + SM_X);
    float* sCa = (float*)(sm + SM_CA);
    float* sCb = (float*)(sm + SM_CB);
    float* sRd = (float*)(sm + SM_RED);

    // ---- per-CTA prep ----
    // Column order: n = wn2*32 + j*8 + c; gate = j; d = wn2*8 + c; W row = j*64 + d.
    {
        int n = tid;                // 0..255
        int wn2 = n >> 5;
        int j = (n >> 3) & 3;
        int c = n & 7;
        int d  = wn2*8 + c;
        int wr = j*64 + d;
        float sa = 0.f, sc = 0.f;
        #pragma unroll 8
        for (int k = 0; k < DD; k++){
            float w = __ldg(W_ih + wr*(2*DD) + k);
            sa += w * __ldg(W_num + k);
            sc += w * __ldg(b_num + k);
        }
        sCa[n] = sa;
        sCb[n] = sc + __ldg(b_ih + wr) + __ldg(b_hh + wr);
        #pragma unroll 8
        for (int k = 0; k < DD; k++){
            float w = __ldg(W_hh + wr*DD + k);
            u32 off = (u32)n*128 + (u32)k*2;
            u32 sw  = off ^ (((u32)n & 7u) << 4);
            *(__half*)(sm + SM_BH + sw) = __float2half_rn(w);
        }
        uint4 z = make_uint4(0,0,0,0);
        uint4* da = (uint4*)(sm + SM_A0);
        for (int i = tid; i < 1024; i += NTHR) da[i] = z;   // A0+A1 (16KB)
        for (int idx = tid; idx < MROWS*LL; idx += NTHR){
            int rr = idx >> 7, tt = idx & 127;
            sXf[rr*129 + tt] = x[(size_t)(r0 + rr)*LL + tt];
        }
        if (tid < 128) sRd[tid] = 0.f;
    }
    __syncthreads();

    // ---- stationary B fragments ----
    u32 breg[4][4][2];
    {
        const char* Bh0 = sm + SM_BH + (size_t)((wn*32 + g) * 128);
        #pragma unroll
        for (int k4 = 0; k4 < 4; k4++){
            u32 o0 = ((u32)(32*k4 + 4*tq)) ^ xorv;
            u32 o8 = o0 ^ 16u;
            #pragma unroll
            for (int j = 0; j < 4; j++){
                breg[j][k4][0] = *(const u32*)(Bh0 + j*1024 + o0);
                breg[j][k4][1] = *(const u32*)(Bh0 + j*1024 + o8);
            }
        }
    }
    // ---- hoisted gate constants ----
    float2 aJ[4], cJ[4];
    #pragma unroll
    for (int j = 0; j < 4; j++){
        int nI = wn*32 + j*8 + 2*tq;
        aJ[j] = *(const float2*)(sCa + nI);
        cJ[j] = *(const float2*)(sCb + nI);
    }

    float creg[16];
    #pragma unroll
    for (int i = 0; i < 16; i++) creg[i] = 0.f;

    const u32 cbS = ((u32)(wn*16 + 4*tq)) ^ xorv;
    const float zf[4] = {0.f, 0.f, 0.f, 0.f};

    for (int t = 0; t < LL; t++){
        const char* Ah = sm + ((t & 1) ? SM_A1 : SM_A0);
        char* Aw = sm + ((t & 1) ? SM_A0 : SM_A1);

        float P2a[4][4], Q2a[4][4], P2b[4][4], Q2b[4][4];

        // sub-block MMA: rows sub*16..+15, chain depth 2, two parallel chains
        auto do_mma = [&](int sub, float P2[4][4], float Q2[4][4]){
            const char* Ar = Ah + (sub*16 + g)*128;
            u32 a[4][4];
            #pragma unroll
            for (int k4 = 0; k4 < 4; k4++){
                u32 o0 = ((u32)(32*k4 + 4*tq)) ^ xorv;
                u32 o8 = o0 ^ 16u;
                a[k4][0] = *(const u32*)(Ar +        o0);
                a[k4][1] = *(const u32*)(Ar + 1024 + o0);
                a[k4][2] = *(const u32*)(Ar +        o8);
                a[k4][3] = *(const u32*)(Ar + 1024 + o8);
            }
            #pragma unroll
            for (int j = 0; j < 4; j++){
                float P[4], Q[4];
                mma_dc(P,     zf,   a[0], breg[j][0]);
                mma_dc(Q,     zf,   a[1], breg[j][1]);
                mma_dc(P2[j], P,    a[2], breg[j][2]);
                mma_dc(Q2[j], Q,    a[3], breg[j][3]);
            }
        };
        auto do_epi = [&](int sub, float P2[4][4], float Q2[4][4]){
            #pragma unroll
            for (int s = 0; s < 2; s++){
                int r = sub*16 + g + s*8;
                float xv = sXf[r*129 + t];
                float h2[2];
                #pragma unroll
                for (int u = 0; u < 2; u++){
                    int fi = s*2 + u;
                    float gi = P2[0][fi] + Q2[0][fi] + fmaf(u?aJ[0].y:aJ[0].x, xv, u?cJ[0].y:cJ[0].x);
                    float gf = P2[1][fi] + Q2[1][fi] + fmaf(u?aJ[1].y:aJ[1].x, xv, u?cJ[1].y:cJ[1].x);
                    float gg = P2[2][fi] + Q2[2][fi] + fmaf(u?aJ[2].y:aJ[2].x, xv, u?cJ[2].y:cJ[2].x);
                    float go = P2[3][fi] + Q2[3][fi] + fmaf(u?aJ[3].y:aJ[3].x, xv, u?cJ[3].y:cJ[3].x);
                    int ci = sub*4 + s*2 + u;
                    float c2 = siga(gf)*creg[ci] + siga(gi)*tanha(gg);
                    creg[ci] = c2;
                    h2[u] = siga(go)*tanha(c2);
                }
                __half b0 = __float2half_rn(h2[0]);
                __half b1 = __float2half_rn(h2[1]);
                u32 hp = (u32)__half_as_ushort(b0) | ((u32)__half_as_ushort(b1) << 16);
                *(u32*)(Aw + r*128 + cbS) = hp;
            }
        };

        // 2-stage pipeline: every epilogue overlaps an independent MMA batch
        do_mma(0, P2a, Q2a);
        do_mma(1, P2b, Q2b);
        do_epi(0, P2a, Q2a);
        do_mma(2, P2a, Q2a);
        do_epi(1, P2b, Q2b);
        do_mma(3, P2b, Q2b);
        do_epi(2, P2a, Q2a);
        do_epi(3, P2b, Q2b);

        __syncthreads();
    }

    // ---- final per-CTA stage ----
    float* sHfin = (float*)(sm + SM_X);            // [row][d] stride 64
    float* sCst  = (float*)(sm + SM_X + 16384);
    #pragma unroll
    for (int sub = 0; sub < 4; sub++){
        #pragma unroll
        for (int s = 0; s < 2; s++){
            #pragma unroll
            for (int u = 0; u < 2; u++){
                int r = sub*16 + g + s*8;
                int d = wn*8 + 2*tq + u;
                u32 sw = ((u32)(2*d)) ^ xorv;
                float h = __half2float(*(const __half*)(sm + SM_A0 + r*128 + sw));
                sHfin[r*64 + d] = h;
                sCst [r*64 + d] = creg[sub*4 + s*2 + u];
            }
        }
    }
    __syncthreads();
    float* sWa = (float*)(sm + SM_BH);
    float* sWf = sWa + 4096;
    for (int i = tid; i < 4096; i += NTHR){ sWa[i] = W_aout[i]; sWf[i] = W_fh[i]; }
    __syncthreads();

    float* sHhat = (float*)(sm + SM_A0);           // [row][d] stride 64 (16KB = A0+A1)
    const int row = tid >> 2;
    const int d0  = (tid & 3) << 4;
    #pragma unroll 2
    for (int jj = 0; jj < 16; jj++){
        int d = d0 + jj;
        float acc2 = __ldg(b_aout + d);
        #pragma unroll 8
        for (int e = 0; e < DD; e++) acc2 += sHfin[row*64 + e] * sWa[d*64 + e];
        sHhat[row*64 + d] = acc2;
        atomicAdd(&sRd[64 + d], acc2);
    }
    __syncthreads();
    #pragma unroll 2
    for (int jj = 0; jj < 16; jj++){
        int d = d0 + jj;
        float f = __ldg(b_fh + d);
        #pragma unroll 8
        for (int e = 0; e < DD; e++) f += sHhat[row*64 + e] * sWf[d*64 + e];
        atomicAdd(&sRd[d], sigf(f) * sCst[row*64 + d]);
    }
    __syncthreads();

    // ---- global reduction + last-CTA finisher ----
    if (tid < 128) atomicAdd(&g_acc[tid], sRd[tid]);
    __threadfence();
    __syncthreads();
    if (tid == 0){
        unsigned int rnk = atomicAdd(&g_ctr, 1);
        *(u32*)(sm + SM_FLG) = (rnk == NBLK - 1) ? 1u : 0u;
    }
    __syncthreads();
    if (*(const u32*)(sm + SM_FLG)){
        float* sfc = (float*)(sm + SM_FIN);
        float* shs = sfc + 64;
        float* sho = sfc + 128;
        if (tid < 64){ sfc[tid] = g_acc[tid]; shs[tid] = g_acc[64 + tid]; }
        __syncthreads();
        if (tid < 64){
            int d = tid;
            float vi = __ldg(b_iouh + d), vo = __ldg(b_iouh + 64 + d), vu = __ldg(b_iouh + 128 + d);
            #pragma unroll 8
            for (int e = 0; e < DD; e++){
                float h = shs[e];
                vi += h * __ldg(W_iouh + (      d)*64 + e);
                vo += h * __ldg(W_iouh + ( 64 + d)*64 + e);
                vu += h * __ldg(W_iouh + (128 + d)*64 + e);
            }
            float cobj = sigf(vi)*tanhp(vu) + sfc[d];
            sho[d] = sigf(vo)*tanhp(cobj);
            out[64 + d] = cobj;
        }
        __syncthreads();
        if (tid < 64){
            int d = tid;
            float acc3 = __ldg(b_oout + d);
            #pragma unroll 8
            for (int e = 0; e < DD; e++) acc3 += sho[e] * __ldg(W_oout + d*64 + e);
            out[d] = acc3;
        }
        if (tid < 128) g_acc[tid] = 0.f;
        __threadfence();
        if (tid == 0) g_ctr = 0;
    }
}

extern "C" void kernel_launch(void* const* d_in, const int* in_sizes, int n_in,
                              void* d_out, int out_size){
    const float* x      = (const float*)d_in[0];
    const float* W_num  = (const float*)d_in[1];
    const float* b_num  = (const float*)d_in[2];
    const float* W_ih   = (const float*)d_in[3];
    const float* W_hh   = (const float*)d_in[4];
    const float* b_ih   = (const float*)d_in[5];
    const float* b_hh   = (const float*)d_in[6];
    const float* W_aout = (const float*)d_in[7];
    const float* b_aout = (const float*)d_in[8];
    const float* W_fh   = (const float*)d_in[9];
    const float* b_fh   = (const float*)d_in[10];
    const float* W_iouh = (const float*)d_in[11];
    const float* b_iouh = (const float*)d_in[12];
    const float* W_oout = (const float*)d_in[13];
    const float* b_oout = (const float*)d_in[14];
    float* out = (float*)d_out;

    cudaFuncSetAttribute(lstm_kernel, cudaFuncAttributeMaxDynamicSharedMemorySize, SM_TOT);

    lstm_kernel<<<NBLK, NTHR, SM_TOT>>>(x, W_num, b_num, W_ih, W_hh, b_ih, b_hh,
                                        W_aout, b_aout, W_fh, b_fh,
                                        W_iouh, b_iouh, W_oout, b_oout, out);
}

// round 16
// speedup vs baseline: 1.2987x; 1.0515x over previous
#include <cuda_runtime.h>
#include <cuda_fp16.h>
#include <cstdint>

#define DD 64
#define LL 128
#define KROWS 8192
#define MROWS 64
#define NBLK (KROWS/MROWS)   // 128 CTAs
#define NTHR 256

typedef unsigned int u32;

// smem byte offsets
#define SM_A0  0          // h buf0: 64 rows x 128B (fp16)
#define SM_A1  8192
#define SM_BH  16384      // W fp16 staging: 256 n-rows x 128B (32KB); reused for sWa/sWf
#define SM_X   49152      // x: 64 x 129 floats = 33024B
#define SM_CA  82176      // 256 floats
#define SM_CB  83200      // 256 floats
#define SM_RED 84224      // 128 floats
#define SM_FIN 84736      // 3*64 floats
#define SM_FLG 85504      // 4B
#define SM_TOT 85568

__device__ float g_acc[128];
__device__ unsigned int g_ctr = 0;

__device__ __forceinline__ float fexp(float x){
    x = fmaxf(fminf(x, 30.f), -30.f);
    return __expf(x);
}
__device__ __forceinline__ float sigf(float x){
    return __fdividef(1.0f, 1.0f + fexp(-x));
}
__device__ __forceinline__ float tanhp(float x){
    return 2.0f * __fdividef(1.0f, 1.0f + fexp(-2.0f*x)) - 1.0f;
}

// packed f16x2 tanh (one MUFU for two activations)
__device__ __forceinline__ u32 h2tanh(u32 x){
    u32 r; asm("tanh.approx.f16x2 %0, %1;" : "=r"(r) : "r"(x)); return r;
}
__device__ __forceinline__ u32 packh2(float lo, float hi){
    u32 r; asm("cvt.rn.f16x2.f32 %0, %1, %2;" : "=r"(r) : "f"(hi), "f"(lo)); return r;
}
__device__ __forceinline__ float h2lo(u32 v){
    __half h = __ushort_as_half((unsigned short)(v & 0xffff));
    return __half2float(h);
}
__device__ __forceinline__ float h2hi(u32 v){
    __half h = __ushort_as_half((unsigned short)(v >> 16));
    return __half2float(h);
}

// D = A*B + C with D possibly != C  (chain-splitting form)
__device__ __forceinline__ void mma_dc(float* d, const float* c, const u32* a, const u32* b){
    asm volatile("mma.sync.aligned.m16n8k16.row.col.f32.f16.f16.f32 "
        "{%0,%1,%2,%3}, {%4,%5,%6,%7}, {%8,%9}, {%10,%11,%12,%13};\n"
        : "=f"(d[0]),"=f"(d[1]),"=f"(d[2]),"=f"(d[3])
        : "r"(a[0]),"r"(a[1]),"r"(a[2]),"r"(a[3]), "r"(b[0]),"r"(b[1]),
          "f"(c[0]),"f"(c[1]),"f"(c[2]),"f"(c[3]));
}

#define LDSM4(r0,r1,r2,r3, a) asm volatile( \
    "ldmatrix.sync.aligned.m8n8.x4.shared.b16 {%0,%1,%2,%3}, [%4];" \
    : "=r"(r0),"=r"(r1),"=r"(r2),"=r"(r3) : "r"(a))

__device__ __forceinline__ u32 smem_u32(const void* p){
    u32 a;
    asm("{ .reg .u64 t; cvta.to.shared.u64 t, %1; cvt.u32.u64 %0, t; }" : "=r"(a) : "l"(p));
    return a;
}

// ---------- fused kernel: weight-stationary, chain-split MMA, f16x2 activations ----------
__global__ void __launch_bounds__(NTHR,1)
lstm_kernel(const float* __restrict__ x,
            const float* __restrict__ W_num,  const float* __restrict__ b_num,
            const float* __restrict__ W_ih,   const float* __restrict__ W_hh,
            const float* __restrict__ b_ih,   const float* __restrict__ b_hh,
            const float* __restrict__ W_aout, const float* __restrict__ b_aout,
            const float* __restrict__ W_fh,   const float* __restrict__ b_fh,
            const float* __restrict__ W_iouh, const float* __restrict__ b_iouh,
            const float* __restrict__ W_oout, const float* __restrict__ b_oout,
            float* __restrict__ out){
    extern __shared__ char sm[];
    const int tid  = threadIdx.x;
    const int wid  = tid >> 5;
    const int lane = tid & 31;
    const int g    = lane >> 2;      // 0..7
    const int tq   = lane & 3;       // 0..3
    const int wn   = wid;            // n 32-col chunk 0..7 ; warp covers all 64 rows
    const u32 xorv = (u32)g << 4;
    const int r0   = blockIdx.x * MROWS;

    float* sXf = (float*)(sm + SM_X);
    float* sCa = (float*)(sm + SM_CA);
    float* sCb = (float*)(sm + SM_CB);
    float* sRd = (float*)(sm + SM_RED);

    // ---- per-CTA prep ----
    // Column order: n = wn2*32 + j*8 + c; gate = j (0=i,1=f,2=g,3=o); d = wn2*8 + c.
    // Gates i,f,o pre-scaled by 0.5 (sigmoid = 0.5*tanh(g/2)+0.5 with the /2 folded in).
    {
        int n = tid;                // 0..255
        int wn2 = n >> 5;
        int j = (n >> 3) & 3;
        int c = n & 7;
        int d  = wn2*8 + c;
        int wr = j*64 + d;
        float scale = (j == 2) ? 1.0f : 0.5f;
        float sa = 0.f, sc = 0.f;
        #pragma unroll 8
        for (int k = 0; k < DD; k++){
            float w = __ldg(W_ih + wr*(2*DD) + k);
            sa += w * __ldg(W_num + k);
            sc += w * __ldg(b_num + k);
        }
        sCa[n] = sa * scale;
        sCb[n] = (sc + __ldg(b_ih + wr) + __ldg(b_hh + wr)) * scale;
        #pragma unroll 8
        for (int k = 0; k < DD; k++){
            float w = __ldg(W_hh + wr*DD + k) * scale;
            u32 off = (u32)n*128 + (u32)k*2;
            u32 sw  = off ^ (((u32)n & 7u) << 4);
            *(__half*)(sm + SM_BH + sw) = __float2half_rn(w);
        }
        uint4 z = make_uint4(0,0,0,0);
        uint4* da = (uint4*)(sm + SM_A0);
        for (int i = tid; i < 1024; i += NTHR) da[i] = z;   // A0+A1 (16KB)
        for (int idx = tid; idx < MROWS*LL; idx += NTHR){
            int rr = idx >> 7, tt = idx & 127;
            sXf[rr*129 + tt] = x[(size_t)(r0 + rr)*LL + tt];
        }
        if (tid < 128) sRd[tid] = 0.f;
    }
    __syncthreads();

    // ---- stationary B fragments ----
    u32 breg[4][4][2];
    {
        const char* Bh0 = sm + SM_BH + (size_t)((wn*32 + g) * 128);
        #pragma unroll
        for (int k4 = 0; k4 < 4; k4++){
            u32 o0 = ((u32)(32*k4 + 4*tq)) ^ xorv;
            u32 o8 = o0 ^ 16u;
            #pragma unroll
            for (int j = 0; j < 4; j++){
                breg[j][k4][0] = *(const u32*)(Bh0 + j*1024 + o0);
                breg[j][k4][1] = *(const u32*)(Bh0 + j*1024 + o8);
            }
        }
    }
    // ---- hoisted gate constants ----
    float2 aJ[4], cJ[4];
    #pragma unroll
    for (int j = 0; j < 4; j++){
        int nI = wn*32 + j*8 + 2*tq;
        aJ[j] = *(const float2*)(sCa + nI);
        cJ[j] = *(const float2*)(sCb + nI);
    }

    float creg[16];
    #pragma unroll
    for (int i = 0; i < 16; i++) creg[i] = 0.f;

    const u32 cbS = ((u32)(wn*16 + 4*tq)) ^ xorv;
    const float zf[4] = {0.f, 0.f, 0.f, 0.f};
    const u32 A0S = smem_u32(sm + SM_A0);
    const u32 A1S = smem_u32(sm + SM_A1);
    // ldmatrix lane offsets: lrow = matrix-row assignment, offk[k4] = swizzled k offset
    const int lrow = (lane & 7) | (((lane >> 3) & 1) << 3);
    const u32 kadd = (u32)((lane >> 4) << 4);          // 0 or 16 bytes (k-hi half)
    u32 offk[4];
    #pragma unroll
    for (int k4 = 0; k4 < 4; k4++)
        offk[k4] = (u32)(32*k4 + kadd) ^ (((u32)lane & 7u) << 4);
    const u32 lrow128 = (u32)(lrow * 128);

    for (int t = 0; t < LL; t++){
        const u32 AhS = (t & 1) ? A1S : A0S;
        char* Aw = sm + ((t & 1) ? SM_A0 : SM_A1);

        float P2a[4][4], Q2a[4][4], P2b[4][4], Q2b[4][4];

        // sub-block MMA: rows sub*16..+15, chain depth 2, two parallel chains
        auto do_mma = [&](int sub, float P2[4][4], float Q2[4][4]){
            const u32 Abase = AhS + (u32)(sub*2048) + lrow128;
            u32 a[4][4];
            #pragma unroll
            for (int k4 = 0; k4 < 4; k4++)
                LDSM4(a[k4][0], a[k4][1], a[k4][2], a[k4][3], Abase + offk[k4]);
            #pragma unroll
            for (int j = 0; j < 4; j++){
                float P[4], Q[4];
                mma_dc(P,     zf,   a[0], breg[j][0]);
                mma_dc(Q,     zf,   a[1], breg[j][1]);
                mma_dc(P2[j], P,    a[2], breg[j][2]);
                mma_dc(Q2[j], Q,    a[3], breg[j][3]);
            }
        };
        auto do_epi = [&](int sub, float P2[4][4], float Q2[4][4]){
            #pragma unroll
            for (int s = 0; s < 2; s++){
                int r = sub*16 + g + s*8;
                float xv = sXf[r*129 + t];
                float G[4][2];
                #pragma unroll
                for (int j = 0; j < 4; j++){
                    #pragma unroll
                    for (int u = 0; u < 2; u++){
                        int fi = s*2 + u;
                        G[j][u] = P2[j][fi] + Q2[j][fi]
                                + fmaf(u ? aJ[j].y : aJ[j].x, xv, u ? cJ[j].y : cJ[j].x);
                    }
                }
                // packed activations: i,f,o pre-scaled by 0.5; g unscaled
                u32 ti2 = h2tanh(packh2(G[0][0], G[0][1]));
                u32 tf2 = h2tanh(packh2(G[1][0], G[1][1]));
                u32 tg2 = h2tanh(packh2(G[2][0], G[2][1]));
                u32 to2 = h2tanh(packh2(G[3][0], G[3][1]));
                int ci0 = sub*4 + s*2;
                float sigi0 = fmaf(h2lo(ti2), 0.5f, 0.5f);
                float sigi1 = fmaf(h2hi(ti2), 0.5f, 0.5f);
                float sigf0 = fmaf(h2lo(tf2), 0.5f, 0.5f);
                float sigf1 = fmaf(h2hi(tf2), 0.5f, 0.5f);
                float c20 = fmaf(sigf0, creg[ci0    ], sigi0 * h2lo(tg2));
                float c21 = fmaf(sigf1, creg[ci0 + 1], sigi1 * h2hi(tg2));
                creg[ci0    ] = c20;
                creg[ci0 + 1] = c21;
                u32 tc2 = h2tanh(packh2(c20, c21));
                // sig(o) and h entirely in half2: h = sig(o) * tanh(c2)
                __half2 so2 = __hfma2(*(__half2*)&to2, __float2half2_rn(0.5f), __float2half2_rn(0.5f));
                __half2 h2v = __hmul2(so2, *(__half2*)&tc2);
                *(u32*)(Aw + r*128 + cbS) = *(u32*)&h2v;
            }
        };

        // 2-stage pipeline: every epilogue overlaps an independent MMA batch
        do_mma(0, P2a, Q2a);
        do_mma(1, P2b, Q2b);
        do_epi(0, P2a, Q2a);
        do_mma(2, P2a, Q2a);
        do_epi(1, P2b, Q2b);
        do_mma(3, P2b, Q2b);
        do_epi(2, P2a, Q2a);
        do_epi(3, P2b, Q2b);

        __syncthreads();
    }

    // ---- final per-CTA stage ----
    float* sHfin = (float*)(sm + SM_X);            // [row][d] stride 64
    float* sCst  = (float*)(sm + SM_X + 16384);
    #pragma unroll
    for (int sub = 0; sub < 4; sub++){
        #pragma unroll
        for (int s = 0; s < 2; s++){
            #pragma unroll
            for (int u = 0; u < 2; u++){
                int r = sub*16 + g + s*8;
                int d = wn*8 + 2*tq + u;
                u32 sw = ((u32)(2*d)) ^ xorv;
                float h = __half2float(*(const __half*)(sm + SM_A0 + r*128 + sw));
                sHfin[r*64 + d] = h;
                sCst [r*64 + d] = creg[sub*4 + s*2 + u];
            }
        }
    }
    __syncthreads();
    float* sWa = (float*)(sm + SM_BH);
    float* sWf = sWa + 4096;
    for (int i = tid; i < 4096; i += NTHR){ sWa[i] = W_aout[i]; sWf[i] = W_fh[i]; }
    __syncthreads();

    float* sHhat = (float*)(sm + SM_A0);           // [row][d] stride 64 (16KB = A0+A1)
    const int row = tid >> 2;
    const int d0  = (tid & 3) << 4;
    #pragma unroll 2
    for (int jj = 0; jj < 16; jj++){
        int d = d0 + jj;
        float acc2 = __ldg(b_aout + d);
        #pragma unroll 8
        for (int e = 0; e < DD; e++) acc2 += sHfin[row*64 + e] * sWa[d*64 + e];
        sHhat[row*64 + d] = acc2;
        atomicAdd(&sRd[64 + d], acc2);
    }
    __syncthreads();
    #pragma unroll 2
    for (int jj = 0; jj < 16; jj++){
        int d = d0 + jj;
        float f = __ldg(b_fh + d);
        #pragma unroll 8
        for (int e = 0; e < DD; e++) f += sHhat[row*64 + e] * sWf[d*64 + e];
        atomicAdd(&sRd[d], sigf(f) * sCst[row*64 + d]);
    }
    __syncthreads();

    // ---- global reduction + last-CTA finisher ----
    if (tid < 128) atomicAdd(&g_acc[tid], sRd[tid]);
    __threadfence();
    __syncthreads();
    if (tid == 0){
        unsigned int rnk = atomicAdd(&g_ctr, 1);
        *(u32*)(sm + SM_FLG) = (rnk == NBLK - 1) ? 1u : 0u;
    }
    __syncthreads();
    if (*(const u32*)(sm + SM_FLG)){
        float* sfc = (float*)(sm + SM_FIN);
        float* shs = sfc + 64;
        float* sho = sfc + 128;
        if (tid < 64){ sfc[tid] = g_acc[tid]; shs[tid] = g_acc[64 + tid]; }
        __syncthreads();
        if (tid < 64){
            int d = tid;
            float vi = __ldg(b_iouh + d), vo = __ldg(b_iouh + 64 + d), vu = __ldg(b_iouh + 128 + d);
            #pragma unroll 8
            for (int e = 0; e < DD; e++){
                float h = shs[e];
                vi += h * __ldg(W_iouh + (      d)*64 + e);
                vo += h * __ldg(W_iouh + ( 64 + d)*64 + e);
                vu += h * __ldg(W_iouh + (128 + d)*64 + e);
            }
            float cobj = sigf(vi)*tanhp(vu) + sfc[d];
            sho[d] = sigf(vo)*tanhp(cobj);
            out[64 + d] = cobj;
        }
        __syncthreads();
        if (tid < 64){
            int d = tid;
            float acc3 = __ldg(b_oout + d);
            #pragma unroll 8
            for (int e = 0; e < DD; e++) acc3 += sho[e] * __ldg(W_oout + d*64 + e);
            out[d] = acc3;
        }
        if (tid < 128) g_acc[tid] = 0.f;
        __threadfence();
        if (tid == 0) g_ctr = 0;
    }
}

extern "C" void kernel_launch(void* const* d_in, const int* in_sizes, int n_in,
                              void* d_out, int out_size){
    const float* x      = (const float*)d_in[0];
    const float* W_num  = (const float*)d_in[1];
    const float* b_num  = (const float*)d_in[2];
    const float* W_ih   = (const float*)d_in[3];
    const float* W_hh   = (const float*)d_in[4];
    const float* b_ih   = (const float*)d_in[5];
    const float* b_hh   = (const float*)d_in[6];
    const float* W_aout = (const float*)d_in[7];
    const float* b_aout = (const float*)d_in[8];
    const float* W_fh   = (const float*)d_in[9];
    const float* b_fh   = (const float*)d_in[10];
    const float* W_iouh = (const float*)d_in[11];
    const float* b_iouh = (const float*)d_in[12];
    const float* W_oout = (const float*)d_in[13];
    const float* b_oout = (const float*)d_in[14];
    float* out = (float*)d_out;

    cudaFuncSetAttribute(lstm_kernel, cudaFuncAttributeMaxDynamicSharedMemorySize, SM_TOT);

    lstm_kernel<<<NBLK, NTHR, SM_TOT>>>(x, W_num, b_num, W_ih, W_hh, b_ih, b_hh,
                                        W_aout, b_aout, W_fh, b_fh,
                                        W_iouh, b_iouh, W_oout, b_oout, out);
}